// round 14
// baseline (speedup 1.0000x reference)
#include <cuda_runtime.h>
#include <cuda_fp16.h>
#include <math.h>
#include <stdint.h>

// Problem constants
#define ROWS   4096          // B*S
#define DMODEL 2048
#define NPROJ  8192          // 4*DMODEL
#define HEADS  16
#define HD     128
#define SEQ    2048
#define NB     2
#define FP16MAX 65504.0f
#define RMS_EPS 1e-5f
// 1/sqrt(128) * log2(e): q pre-scale so softmax can use exp2 directly
#define ATTN_SCALE_L2E (0.08838834764831845f * 1.4426950408889634f)

// ---------------- scratch (allocation-free) ----------------
#define HSD ((size_t)NB * HEADS * SEQ * HD)
__device__ __half g_qh[HSD];                 // q fp16 (rmsnorm*scale*log2e folded)
__device__ __half g_kh[HSD];                 // k fp16
__device__ __half g_vh[HSD];                 // v fp16
__device__ __half g_gate[HSD];               // gate fp16
__device__ __half g_ah  [(size_t)ROWS * DMODEL];   // hidden rounded fp16
__device__ __half g_win [(size_t)NPROJ * DMODEL];  // W_in^T fp16 [N,K]
__device__ __half g_wo  [(size_t)DMODEL * DMODEL]; // W_out^T fp16 [N,K]
__device__ __half g_th  [(size_t)ROWS * DMODEL];   // attn out rounded fp16

// ---------------- PTX helpers (sm_80-portable only) ----------------
__device__ __forceinline__ uint32_t smem_u32(const void* p) {
    uint32_t a;
    asm("{ .reg .u64 t; cvta.to.shared.u64 t, %1; cvt.u32.u64 %0, t; }" : "=r"(a) : "l"(p));
    return a;
}
__device__ __forceinline__ void cp16(uint32_t saddr, const void* g) {
    asm volatile("cp.async.cg.shared.global [%0], [%1], 16;" :: "r"(saddr), "l"(g));
}
__device__ __forceinline__ void cp_commit() {
    asm volatile("cp.async.commit_group;" ::: "memory");
}
template <int N>
__device__ __forceinline__ void cp_wait() {
    asm volatile("cp.async.wait_group %0;" :: "n"(N) : "memory");
}
__device__ __forceinline__ void ldsm4(uint32_t* r, uint32_t a) {
    asm volatile("ldmatrix.sync.aligned.m8n8.x4.shared.b16 {%0,%1,%2,%3}, [%4];"
                 : "=r"(r[0]), "=r"(r[1]), "=r"(r[2]), "=r"(r[3]) : "r"(a));
}
__device__ __forceinline__ void ldsm4t(uint32_t* r, uint32_t a) {
    asm volatile("ldmatrix.sync.aligned.m8n8.x4.trans.shared.b16 {%0,%1,%2,%3}, [%4];"
                 : "=r"(r[0]), "=r"(r[1]), "=r"(r[2]), "=r"(r[3]) : "r"(a));
}
__device__ __forceinline__ void mma16816(float* c, const uint32_t* a, const uint32_t* b) {
    asm volatile(
        "mma.sync.aligned.m16n8k16.row.col.f32.f16.f16.f32 "
        "{%0,%1,%2,%3}, {%4,%5,%6,%7}, {%8,%9}, {%0,%1,%2,%3};"
        : "+f"(c[0]), "+f"(c[1]), "+f"(c[2]), "+f"(c[3])
        : "r"(a[0]), "r"(a[1]), "r"(a[2]), "r"(a[3]), "r"(b[0]), "r"(b[1]));
}
__device__ __forceinline__ uint32_t roundh2(float x, float y) {
    __half2 h2 = __floats2half2_rn(x, y);
    return *(uint32_t*)&h2;
}
__device__ __forceinline__ float exp2fa(float x) {
    float r;
    asm("ex2.approx.f32 %0, %1;" : "=f"(r) : "f"(x));
    return r;
}

// ---------------- fused prep kernel ----------------
#define WIN_TX (NPROJ / 32)                    // 256
#define WIN_TILES (WIN_TX * (DMODEL / 32))     // 16384
#define WO_TX (DMODEL / 32)                    // 64
#define WO_TILES (WO_TX * (DMODEL / 32))       // 4096
#define HID_BLKS 1024
#define PREP_BLKS (WIN_TILES + WO_TILES + HID_BLKS)

__global__ __launch_bounds__(256)
void prep_all(const float* __restrict__ hidden,
              const float* __restrict__ W_in,
              const float* __restrict__ W_out)
{
    const int bid = blockIdx.x;
    const int tid = threadIdx.x;

    if (bid < WIN_TILES + WO_TILES) {
        __shared__ float t[32][33];
        const float* in;
        __half* outp;
        int bx, by, R, C;
        if (bid < WIN_TILES) {
            in = W_in; outp = g_win; R = DMODEL; C = NPROJ;
            bx = (bid % WIN_TX) * 32; by = (bid / WIN_TX) * 32;
        } else {
            const int i2 = bid - WIN_TILES;
            in = W_out; outp = g_wo; R = DMODEL; C = DMODEL;
            bx = (i2 % WO_TX) * 32; by = (i2 / WO_TX) * 32;
        }
        const int tx = tid & 31, ty = tid >> 5;
#pragma unroll
        for (int j = 0; j < 4; ++j)
            t[ty + 8 * j][tx] = in[(size_t)(by + ty + 8 * j) * C + bx + tx];
        __syncthreads();
#pragma unroll
        for (int j = 0; j < 4; ++j) {
            float v = t[tx][ty + 8 * j];
            outp[(size_t)(bx + ty + 8 * j) * R + by + tx] = __float2half_rn(v);
        }
    } else {
        const size_t n4 = (size_t)ROWS * DMODEL / 4;
        size_t i = (size_t)(bid - WIN_TILES - WO_TILES) * 256 + tid;
        const size_t stride = (size_t)HID_BLKS * 256;
        for (; i < n4; i += stride) {
            float4 x = ((const float4*)hidden)[i];
            ((uint32_t*)g_ah)[i * 2 + 0] = roundh2(x.x, x.y);
            ((uint32_t*)g_ah)[i * 2 + 1] = roundh2(x.z, x.w);
        }
    }
}

// ---------------- HMMA fp16 1-term GEMM: C[M,N] = A[M,K] @ B[N,K]^T ----------------
// CTA tile 128x256, BK=64, 8 warps (2m x 4n), warp tile 64x64 (32 FLOP/smem-byte).
#define BM 128
#define BN 256
#define BK 64
#define ROWB 144                    // 64 fp16 = 128 B + 16 pad
#define A_TILEB (BM * ROWB)         // 18432
#define B_TILEB (BN * ROWB)         // 36864
#define STAGEB (A_TILEB + B_TILEB)  // 55296
#define GSMEM (2 * STAGEB)          // 110592

__global__ __launch_bounds__(256, 1)
void gemm_hmma(const __half* __restrict__ A, const __half* __restrict__ B,
               float* __restrict__ C, int M, int N, int K, int mode)
{
    extern __shared__ char smraw[];
    const uint32_t sb = smem_u32(smraw);

    const int tid = threadIdx.x, wid = tid >> 5, lane = tid & 31;
    const int bm = blockIdx.y * BM, bn = blockIdx.x * BN;
    const int wm = wid >> 2, wn = wid & 3;        // 2 x 4 warp grid

    const __half* A_p = A + (size_t)bm * K;
    const __half* B_p = B + (size_t)bn * K;

    const int nk = K / BK;

    auto stage_load = [&](int s, int kc) {
        const uint32_t base = sb + s * STAGEB;
        const size_t kofs = (size_t)kc * BK;
#pragma unroll
        for (int i = 0; i < 4; ++i) {            // A: 128 rows x 8 chunks
            const int v = tid + i * 256;
            const int row = v >> 3, c = v & 7;
            cp16(base + row * ROWB + c * 16, A_p + (size_t)row * K + kofs + c * 8);
        }
#pragma unroll
        for (int i = 0; i < 8; ++i) {            // B: 256 rows x 8 chunks
            const int v = tid + i * 256;
            const int row = v >> 3, c = v & 7;
            cp16(base + A_TILEB + row * ROWB + c * 16,
                 B_p + (size_t)row * K + kofs + c * 8);
        }
    };

    float acc[32][4];                 // [mt*8 + nt][4], mt 0..3, nt 0..7
#pragma unroll
    for (int i = 0; i < 32; ++i)
#pragma unroll
        for (int j = 0; j < 4; ++j) acc[i][j] = 0.f;

    stage_load(0, 0); cp_commit();
    stage_load(1, 1); cp_commit();
    cp_wait<1>();
    __syncthreads();

    for (int c = 0; c < nk; ++c) {
        const int s = c & 1;
        const uint32_t Ah = sb + s * STAGEB;
        const uint32_t Bh = Ah + A_TILEB;

#pragma unroll
        for (int ks = 0; ks < 4; ++ks) {
            uint32_t af[4][4];
#pragma unroll
            for (int mt = 0; mt < 4; ++mt) {
                const uint32_t ro = (uint32_t)(wm * 64 + mt * 16 + (lane & 15)) * ROWB
                                  + ks * 32 + (lane >> 4) * 16;
                ldsm4(af[mt], Ah + ro);
            }
#pragma unroll
            for (int bt = 0; bt < 4; ++bt) {
                const uint32_t ro = (uint32_t)(wn * 64 + bt * 16 + (lane & 15)) * ROWB
                                  + ks * 32 + (lane >> 4) * 16;
                uint32_t bf[4];
                ldsm4(bf, Bh + ro);
                const uint32_t b0[2] = { bf[0], bf[2] }, b1[2] = { bf[1], bf[3] };
#pragma unroll
                for (int mt = 0; mt < 4; ++mt) {
                    mma16816(acc[mt * 8 + bt * 2 + 0], af[mt], b0);
                    mma16816(acc[mt * 8 + bt * 2 + 1], af[mt], b1);
                }
            }
        }

        __syncthreads();
        if (c + 2 < nk) {
            stage_load(s, c + 2);
            cp_commit();
            cp_wait<1>();
        } else {
            cp_wait<0>();
        }
        __syncthreads();
    }

    const int group = bn >> 11;       // constant per CTA (BN=256 divides 2048)

    // ---- fused clamp+RMSNorm for q,k (mode 1) ----
    // Heads are 128 cols = 2 adjacent n-warps (wn pairs {0,1},{2,3}).
    float* ssm = (float*)smraw;       // [4][128]
    if (mode && group < 2) {
        float ssp[4][2];
#pragma unroll
        for (int mt = 0; mt < 4; ++mt) { ssp[mt][0] = 0.f; ssp[mt][1] = 0.f; }
#pragma unroll
        for (int mt = 0; mt < 4; ++mt)
#pragma unroll
            for (int nt = 0; nt < 8; ++nt) {
                float* a = acc[mt * 8 + nt];
#pragma unroll
                for (int q = 0; q < 4; ++q) {
                    float v = fminf(fmaxf(a[q], -FP16MAX), FP16MAX);
                    a[q] = v;
                    ssp[mt][q >> 1] += v * v;
                }
            }
#pragma unroll
        for (int mt = 0; mt < 4; ++mt)
#pragma unroll
            for (int rr = 0; rr < 2; ++rr) {
                float s0 = ssp[mt][rr];
                s0 += __shfl_xor_sync(0xffffffffu, s0, 1);
                s0 += __shfl_xor_sync(0xffffffffu, s0, 2);
                if ((lane & 3) == 0) {
                    const int row = wm * 64 + mt * 16 + (lane >> 2) + rr * 8;
                    ssm[wn * 128 + row] = s0;
                }
            }
        __syncthreads();
        const float post = (group == 0) ? ATTN_SCALE_L2E : 1.0f;
        const int pair = wn & 2;      // head-pair base (wn 0,1 -> 0; wn 2,3 -> 2)
#pragma unroll
        for (int mt = 0; mt < 4; ++mt)
#pragma unroll
            for (int rr = 0; rr < 2; ++rr) {
                const int row = wm * 64 + mt * 16 + (lane >> 2) + rr * 8;
                const float tot = ssm[pair * 128 + row] + ssm[(pair + 1) * 128 + row];
                const float sc = rsqrtf(tot * (1.0f / 128.0f) + RMS_EPS) * post;
#pragma unroll
                for (int nt = 0; nt < 8; ++nt) {
                    acc[mt * 8 + nt][rr * 2 + 0] *= sc;
                    acc[mt * 8 + nt][rr * 2 + 1] *= sc;
                }
            }
    }

    if (mode) {
        // q,k,v,gate all fp16. Layout [b][h][s][d].
        __half* dsth = (group == 0) ? g_qh : (group == 1) ? g_kh
                     : (group == 2) ? g_vh : g_gate;
        const int colw = bn + wn * 64;
        const int hh = (colw >> 7) & 15;          // constant per warp
#pragma unroll
        for (int mt = 0; mt < 4; ++mt)
#pragma unroll
            for (int nt = 0; nt < 8; ++nt) {
                const int d = ((colw & 127) + nt * 8 + (lane & 3) * 2);
                float* a = acc[mt * 8 + nt];
#pragma unroll
                for (int rr = 0; rr < 2; ++rr) {
                    const int row = bm + wm * 64 + mt * 16 + (lane >> 2) + rr * 8;
                    const int bb = row >> 11, s = row & 2047;
                    const size_t idx = ((size_t)(bb * HEADS + hh) * SEQ + s) * HD + d;
                    *(uint32_t*)(dsth + idx) = roundh2(a[rr * 2 + 0], a[rr * 2 + 1]);
                }
            }
    } else {
#pragma unroll
        for (int mt = 0; mt < 4; ++mt)
#pragma unroll
            for (int nt = 0; nt < 8; ++nt) {
                const int col = bn + wn * 64 + nt * 8 + (lane & 3) * 2;
                const int r0 = bm + wm * 64 + mt * 16 + (lane >> 2);
                float* a = acc[mt * 8 + nt];
                *(float2*)(C + (size_t)r0 * N + col)       = make_float2(a[0], a[1]);
                *(float2*)(C + (size_t)(r0 + 8) * N + col) = make_float2(a[2], a[3]);
            }
    }
}

// ---------------- HMMA fp16 1-term flash attention (unchanged from R13) ----------------
#define AROWB 272                        // 128 fp16 = 256 B + 16 pad
#define QROWS 256
#define QT (QROWS * AROWB)               // 69632
#define KVR 64
#define KVB (KVR * AROWB)                // 17408
#define STG (2 * KVB)                    // k + v = 34816
#define ATTN_SMEM (QT + 2 * STG)         // 139264

__global__ __launch_bounds__(512, 1)
void attn_hmma()
{
    extern __shared__ char smraw[];
    const uint32_t sb = smem_u32(smraw);

    const int tid = threadIdx.x, w = tid >> 5, lane = tid & 31;
    const int qt = blockIdx.x, h = blockIdx.y, b = blockIdx.z;
    const size_t hb = ((size_t)b * HEADS + h) * SEQ;

    const __half* Qh_g = g_qh + (hb + qt * QROWS) * HD;
    const __half* Kh_g = g_kh + hb * HD;
    const __half* Vh_g = g_vh + hb * HD;

    auto loadKV = [&](int s, int kt) {
        const uint32_t base = sb + QT + s * STG;
        const size_t kv0 = (size_t)kt * KVR;
#pragma unroll
        for (int i = 0; i < 2; ++i) {
            const int v = tid + i * 512;
            const int row = v >> 4, c = v & 15;
            const uint32_t so = base + row * AROWB + c * 16;
            const size_t go = (kv0 + row) * HD + c * 8;
            cp16(so,       Kh_g + go);
            cp16(so + KVB, Vh_g + go);
        }
    };

#pragma unroll
    for (int i = 0; i < 8; ++i) {
        const int v = tid + i * 512;
        const int row = v >> 4, c = v & 15;
        cp16(sb + row * AROWB + c * 16, Qh_g + (size_t)row * HD + c * 8);
    }
    loadKV(0, 0); cp_commit();
    loadKV(1, 1); cp_commit();
    cp_wait<1>();
    __syncthreads();

    float oacc[16][4];
#pragma unroll
    for (int i = 0; i < 16; ++i)
#pragma unroll
        for (int j = 0; j < 4; ++j) oacc[i][j] = 0.f;
    float m0 = -INFINITY, m1 = -INFINITY, l0 = 0.f, l1 = 0.f;

    const int nkt = SEQ / KVR;   // 32
    for (int c = 0; c < nkt; ++c) {
        const int s = c & 1;
        const uint32_t kbase = sb + QT + s * STG;

        float sacc[8][4];
#pragma unroll
        for (int i = 0; i < 8; ++i)
#pragma unroll
            for (int j = 0; j < 4; ++j) sacc[i][j] = 0.f;

#pragma unroll
        for (int kt = 0; kt < 8; ++kt) {
            uint32_t ah[4];
            const uint32_t qo = (uint32_t)(w * 16 + (lane & 15)) * AROWB
                              + kt * 32 + (lane >> 4) * 16;
            ldsm4(ah, sb + qo);
#pragma unroll
            for (int g = 0; g < 4; ++g) {
                const uint32_t ko = kbase + (uint32_t)(g * 16 + (lane & 15)) * AROWB
                                  + kt * 32 + (lane >> 4) * 16;
                uint32_t bh[4];
                ldsm4(bh, ko);
                const uint32_t b0[2] = { bh[0], bh[2] }, b1[2] = { bh[1], bh[3] };
                mma16816(sacc[2 * g + 0], ah, b0);
                mma16816(sacc[2 * g + 1], ah, b1);
            }
        }

        float mx0 = -INFINITY, mx1 = -INFINITY;
#pragma unroll
        for (int j = 0; j < 8; ++j) {
            mx0 = fmaxf(mx0, fmaxf(sacc[j][0], sacc[j][1]));
            mx1 = fmaxf(mx1, fmaxf(sacc[j][2], sacc[j][3]));
        }
        mx0 = fmaxf(mx0, __shfl_xor_sync(0xffffffffu, mx0, 1));
        mx0 = fmaxf(mx0, __shfl_xor_sync(0xffffffffu, mx0, 2));
        mx1 = fmaxf(mx1, __shfl_xor_sync(0xffffffffu, mx1, 1));
        mx1 = fmaxf(mx1, __shfl_xor_sync(0xffffffffu, mx1, 2));
        const float mn0 = fmaxf(m0, mx0), mn1 = fmaxf(m1, mx1);
        const float corr0 = exp2fa(m0 - mn0), corr1 = exp2fa(m1 - mn1);
        m0 = mn0; m1 = mn1;
        float rs0 = 0.f, rs1 = 0.f;
#pragma unroll
        for (int j = 0; j < 8; ++j) {
            sacc[j][0] = exp2fa(sacc[j][0] - mn0);
            sacc[j][1] = exp2fa(sacc[j][1] - mn0);
            sacc[j][2] = exp2fa(sacc[j][2] - mn1);
            sacc[j][3] = exp2fa(sacc[j][3] - mn1);
            rs0 += sacc[j][0] + sacc[j][1];
            rs1 += sacc[j][2] + sacc[j][3];
        }
        rs0 += __shfl_xor_sync(0xffffffffu, rs0, 1);
        rs0 += __shfl_xor_sync(0xffffffffu, rs0, 2);
        rs1 += __shfl_xor_sync(0xffffffffu, rs1, 1);
        rs1 += __shfl_xor_sync(0xffffffffu, rs1, 2);
        l0 = l0 * corr0 + rs0;
        l1 = l1 * corr1 + rs1;
        const bool need = (corr0 != 1.0f) || (corr1 != 1.0f);
        if (__any_sync(0xffffffffu, need)) {
#pragma unroll
            for (int n = 0; n < 16; ++n) {
                oacc[n][0] *= corr0; oacc[n][1] *= corr0;
                oacc[n][2] *= corr1; oacc[n][3] *= corr1;
            }
        }

#pragma unroll
        for (int kc = 0; kc < 4; ++kc) {
            uint32_t pa[4];
            pa[0] = roundh2(sacc[2 * kc][0],     sacc[2 * kc][1]);
            pa[1] = roundh2(sacc[2 * kc][2],     sacc[2 * kc][3]);
            pa[2] = roundh2(sacc[2 * kc + 1][0], sacc[2 * kc + 1][1]);
            pa[3] = roundh2(sacc[2 * kc + 1][2], sacc[2 * kc + 1][3]);
#pragma unroll
            for (int g2 = 0; g2 < 8; ++g2) {
                const uint32_t vo = kbase + KVB
                                  + (uint32_t)(kc * 16 + (lane & 15)) * AROWB
                                  + (g2 * 16 + (lane >> 4) * 8) * 2;
                uint32_t vh[4];
                ldsm4t(vh, vo);
                const uint32_t b0[2] = { vh[0], vh[1] }, b1[2] = { vh[2], vh[3] };
                mma16816(oacc[2 * g2 + 0], pa, b0);
                mma16816(oacc[2 * g2 + 1], pa, b1);
            }
        }

        __syncthreads();
        if (c + 2 < nkt) {
            loadKV(s, c + 2);
            cp_commit();
            cp_wait<1>();
        } else {
            cp_wait<0>();
        }
        __syncthreads();
    }

    const float inv0 = 1.0f / l0, inv1 = 1.0f / l1;
    const int r0 = w * 16 + (lane >> 2);
#pragma unroll
    for (int n = 0; n < 16; ++n) {
        const int d = n * 8 + (lane & 3) * 2;
#pragma unroll
        for (int rr = 0; rr < 2; ++rr) {
            const int qrow = qt * QROWS + r0 + rr * 8;
            const float inv = rr ? inv1 : inv0;
            const uint32_t gw = *(const uint32_t*)(g_gate + (hb + qrow) * HD + d);
            const float2 gv = __half22float2(*(const __half2*)&gw);
            const float sg0 = 1.0f / (1.0f + __expf(-gv.x));
            const float sg1 = 1.0f / (1.0f + __expf(-gv.y));
            const float x = sg0 * oacc[n][rr * 2 + 0] * inv;
            const float y = sg1 * oacc[n][rr * 2 + 1] * inv;
            const size_t o = (size_t)(b * SEQ + qrow) * DMODEL + h * HD + d;
            *(uint32_t*)(g_th + o) = roundh2(x, y);
        }
    }
}

// ---------------------------------------------------------------------------
extern "C" void kernel_launch(void* const* d_in, const int* in_sizes, int n_in,
                              void* d_out, int out_size)
{
    const float* hidden = (const float*)d_in[0];
    const float* W_in   = (const float*)d_in[1];
    const float* W_out  = (const float*)d_in[2];
    float* out = (float*)d_out;

    __half *ah, *win, *wo, *th;
    cudaGetSymbolAddress((void**)&ah,  g_ah);
    cudaGetSymbolAddress((void**)&win, g_win);
    cudaGetSymbolAddress((void**)&wo,  g_wo);
    cudaGetSymbolAddress((void**)&th,  g_th);

    cudaFuncSetAttribute(gemm_hmma,
                         cudaFuncAttributeMaxDynamicSharedMemorySize, GSMEM);
    cudaFuncSetAttribute(attn_hmma,
                         cudaFuncAttributeMaxDynamicSharedMemorySize, ATTN_SMEM);

    // 0) fused prep: hidden->fp16, W_in->fp16 T, W_out->fp16 T (one launch)
    prep_all<<<PREP_BLKS, 256>>>(hidden, W_in, W_out);

    // 1) proj GEMM (1-term fp16, 64x64 warp tiles) -> q/k/v/gate fp16
    gemm_hmma<<<dim3(NPROJ / BN, ROWS / BM), 256, GSMEM>>>(
        ah, win, nullptr, ROWS, NPROJ, DMODEL, 1);

    // 2) fp16 1-term flash attention (exp2 softmax) + sigmoid gate -> g_th
    attn_hmma<<<dim3(SEQ / QROWS, HEADS, NB), 512, ATTN_SMEM>>>();

    // 3) out = att @ W_out (1-term fp16)
    gemm_hmma<<<dim3(DMODEL / BN, ROWS / BM), 256, GSMEM>>>(
        th, wo, out, ROWS, DMODEL, DMODEL, 0);
}

// round 15
// speedup vs baseline: 1.0215x; 1.0215x over previous
#include <cuda_runtime.h>
#include <cuda_fp16.h>
#include <math.h>
#include <stdint.h>

// Problem constants
#define ROWS   4096          // B*S
#define DMODEL 2048
#define NPROJ  8192          // 4*DMODEL
#define HEADS  16
#define HD     128
#define SEQ    2048
#define NB     2
#define FP16MAX 65504.0f
#define RMS_EPS 1e-5f
// 1/sqrt(128) * log2(e): q pre-scale so softmax can use exp2 directly
#define ATTN_SCALE_L2E (0.08838834764831845f * 1.4426950408889634f)

// ---------------- scratch (allocation-free) ----------------
#define HSD ((size_t)NB * HEADS * SEQ * HD)
__device__ __half g_qh[HSD];                 // q fp16 (rmsnorm*scale*log2e folded)
__device__ __half g_kh[HSD];                 // k fp16
__device__ __half g_vh[HSD];                 // v fp16
__device__ __half g_gate[HSD];               // gate fp16
__device__ __half g_ah  [(size_t)ROWS * DMODEL];   // hidden rounded fp16
__device__ __half g_win [(size_t)NPROJ * DMODEL];  // W_in^T fp16 [N,K]
__device__ __half g_wo  [(size_t)DMODEL * DMODEL]; // W_out^T fp16 [N,K]
__device__ __half g_th  [(size_t)ROWS * DMODEL];   // attn out rounded fp16

// ---------------- PTX helpers (sm_80-portable only) ----------------
__device__ __forceinline__ uint32_t smem_u32(const void* p) {
    uint32_t a;
    asm("{ .reg .u64 t; cvta.to.shared.u64 t, %1; cvt.u32.u64 %0, t; }" : "=r"(a) : "l"(p));
    return a;
}
__device__ __forceinline__ void cp16(uint32_t saddr, const void* g) {
    asm volatile("cp.async.cg.shared.global [%0], [%1], 16;" :: "r"(saddr), "l"(g));
}
__device__ __forceinline__ void cp_commit() {
    asm volatile("cp.async.commit_group;" ::: "memory");
}
template <int N>
__device__ __forceinline__ void cp_wait() {
    asm volatile("cp.async.wait_group %0;" :: "n"(N) : "memory");
}
__device__ __forceinline__ void ldsm4(uint32_t* r, uint32_t a) {
    asm volatile("ldmatrix.sync.aligned.m8n8.x4.shared.b16 {%0,%1,%2,%3}, [%4];"
                 : "=r"(r[0]), "=r"(r[1]), "=r"(r[2]), "=r"(r[3]) : "r"(a));
}
__device__ __forceinline__ void ldsm4t(uint32_t* r, uint32_t a) {
    asm volatile("ldmatrix.sync.aligned.m8n8.x4.trans.shared.b16 {%0,%1,%2,%3}, [%4];"
                 : "=r"(r[0]), "=r"(r[1]), "=r"(r[2]), "=r"(r[3]) : "r"(a));
}
__device__ __forceinline__ void mma16816(float* c, const uint32_t* a, const uint32_t* b) {
    asm volatile(
        "mma.sync.aligned.m16n8k16.row.col.f32.f16.f16.f32 "
        "{%0,%1,%2,%3}, {%4,%5,%6,%7}, {%8,%9}, {%0,%1,%2,%3};"
        : "+f"(c[0]), "+f"(c[1]), "+f"(c[2]), "+f"(c[3])
        : "r"(a[0]), "r"(a[1]), "r"(a[2]), "r"(a[3]), "r"(b[0]), "r"(b[1]));
}
__device__ __forceinline__ uint32_t roundh2(float x, float y) {
    __half2 h2 = __floats2half2_rn(x, y);
    return *(uint32_t*)&h2;
}
__device__ __forceinline__ float exp2fa(float x) {
    float r;
    asm("ex2.approx.f32 %0, %1;" : "=f"(r) : "f"(x));
    return r;
}

// ---------------- fused prep kernel ----------------
#define WIN_TX (NPROJ / 32)                    // 256
#define WIN_TILES (WIN_TX * (DMODEL / 32))     // 16384
#define WO_TX (DMODEL / 32)                    // 64
#define WO_TILES (WO_TX * (DMODEL / 32))       // 4096
#define HID_BLKS 1024
#define PREP_BLKS (WIN_TILES + WO_TILES + HID_BLKS)

__global__ __launch_bounds__(256)
void prep_all(const float* __restrict__ hidden,
              const float* __restrict__ W_in,
              const float* __restrict__ W_out)
{
    const int bid = blockIdx.x;
    const int tid = threadIdx.x;

    if (bid < WIN_TILES + WO_TILES) {
        __shared__ float t[32][33];
        const float* in;
        __half* outp;
        int bx, by, R, C;
        if (bid < WIN_TILES) {
            in = W_in; outp = g_win; R = DMODEL; C = NPROJ;
            bx = (bid % WIN_TX) * 32; by = (bid / WIN_TX) * 32;
        } else {
            const int i2 = bid - WIN_TILES;
            in = W_out; outp = g_wo; R = DMODEL; C = DMODEL;
            bx = (i2 % WO_TX) * 32; by = (i2 / WO_TX) * 32;
        }
        const int tx = tid & 31, ty = tid >> 5;
#pragma unroll
        for (int j = 0; j < 4; ++j)
            t[ty + 8 * j][tx] = in[(size_t)(by + ty + 8 * j) * C + bx + tx];
        __syncthreads();
#pragma unroll
        for (int j = 0; j < 4; ++j) {
            float v = t[tx][ty + 8 * j];
            outp[(size_t)(bx + ty + 8 * j) * R + by + tx] = __float2half_rn(v);
        }
    } else {
        const size_t n4 = (size_t)ROWS * DMODEL / 4;
        size_t i = (size_t)(bid - WIN_TILES - WO_TILES) * 256 + tid;
        const size_t stride = (size_t)HID_BLKS * 256;
        for (; i < n4; i += stride) {
            float4 x = ((const float4*)hidden)[i];
            ((uint32_t*)g_ah)[i * 2 + 0] = roundh2(x.x, x.y);
            ((uint32_t*)g_ah)[i * 2 + 1] = roundh2(x.z, x.w);
        }
    }
}

// ---------------- HMMA fp16 1-term GEMM: C[M,N] = A[M,K] @ B[N,K]^T ----------------
// 128x128 block tile, BK=64, 8 warps (4m x 2n), warp tile 32x64.
// Software-pipelined ldsm: fragments loaded one step ahead of their MMAs.
#define BM 128
#define BN 128
#define BK 64
#define ROWB 144                    // 64 fp16 = 128 B + 16 pad
#define TILEB (128 * ROWB)          // 18432 per matrix
#define STAGEB (2 * TILEB)          // A + B = 36864
#define GSMEM (2 * STAGEB)          // 73728

__global__ __launch_bounds__(256)
void gemm_hmma(const __half* __restrict__ A, const __half* __restrict__ B,
               float* __restrict__ C, int M, int N, int K, int mode)
{
    extern __shared__ char smraw[];
    const uint32_t sb = smem_u32(smraw);

    const int tid = threadIdx.x, wid = tid >> 5, lane = tid & 31;
    const int bm = blockIdx.y * BM, bn = blockIdx.x * BN;
    const int wm = wid >> 1, wn = wid & 1;

    const __half* A_p = A + (size_t)bm * K;
    const __half* B_p = B + (size_t)bn * K;

    const int nk = K / BK;

    auto load_mat = [&](uint32_t dst, const __half* src, size_t kofs) {
#pragma unroll
        for (int i = 0; i < 4; ++i) {
            const int v = tid + i * 256;       // 128 rows x 8 chunks = 1024
            const int row = v >> 3, c = v & 7;
            cp16(dst + row * ROWB + c * 16, src + (size_t)row * K + kofs + c * 8);
        }
    };
    auto stage_load = [&](int s, int kc) {
        const uint32_t base = sb + s * STAGEB;
        const size_t kofs = (size_t)kc * BK;
        load_mat(base,         A_p, kofs);
        load_mat(base + TILEB, B_p, kofs);
    };

    float acc[16][4];
#pragma unroll
    for (int i = 0; i < 16; ++i)
#pragma unroll
        for (int j = 0; j < 4; ++j) acc[i][j] = 0.f;

    stage_load(0, 0); cp_commit();
    stage_load(1, 1); cp_commit();
    cp_wait<1>();
    __syncthreads();

    const uint32_t aro = (uint32_t)(wm * 32 + (lane & 15)) * ROWB + (lane >> 4) * 16;
    const uint32_t bro = (uint32_t)(wn * 64 + (lane & 15)) * ROWB + (lane >> 4) * 16;

    for (int c = 0; c < nk; ++c) {
        const int s = c & 1;
        const uint32_t Ah = sb + s * STAGEB;
        const uint32_t Bh = Ah + TILEB;

        uint32_t afb[2][2][4];     // [buf][mt][frag]
        uint32_t bfb[2][4];        // [buf][frag]

        // preload ks=0 A frags and (ks=0, bt=0) B frag
#pragma unroll
        for (int mt = 0; mt < 2; ++mt)
            ldsm4(afb[0][mt], Ah + aro + mt * 16 * ROWB);
        ldsm4(bfb[0], Bh + bro);

#pragma unroll
        for (int ks = 0; ks < 4; ++ks) {
#pragma unroll
            for (int bt = 0; bt < 4; ++bt) {
                const int cur = bt & 1;
                // prefetch next fragments before consuming current ones
                if (bt < 3) {
                    ldsm4(bfb[cur ^ 1], Bh + bro + (bt + 1) * 16 * ROWB + ks * 32);
                } else if (ks < 3) {
#pragma unroll
                    for (int mt = 0; mt < 2; ++mt)
                        ldsm4(afb[(ks + 1) & 1][mt],
                              Ah + aro + mt * 16 * ROWB + (ks + 1) * 32);
                    ldsm4(bfb[cur ^ 1], Bh + bro + (ks + 1) * 32);
                }
                uint32_t* bf = bfb[cur];
                const uint32_t b0[2] = { bf[0], bf[2] }, b1[2] = { bf[1], bf[3] };
#pragma unroll
                for (int mt = 0; mt < 2; ++mt) {
                    mma16816(acc[mt * 8 + bt * 2 + 0], afb[ks & 1][mt], b0);
                    mma16816(acc[mt * 8 + bt * 2 + 1], afb[ks & 1][mt], b1);
                }
            }
        }

        __syncthreads();
        if (c + 2 < nk) {
            stage_load(s, c + 2);
            cp_commit();
            cp_wait<1>();
        } else {
            cp_wait<0>();
        }
        __syncthreads();
    }

    const int group = bn >> 11;       // 0=q 1=k 2=v 3=g (mode 1 only)

    // ---- fused clamp+RMSNorm for q,k (mode 1) ----
    float* ssm = (float*)smraw;
    if (mode && group < 2) {
        float ssp[2][2] = { {0.f, 0.f}, {0.f, 0.f} };
#pragma unroll
        for (int mt = 0; mt < 2; ++mt)
#pragma unroll
            for (int bt = 0; bt < 4; ++bt)
#pragma unroll
                for (int half = 0; half < 2; ++half) {
                    float* a = acc[mt * 8 + bt * 2 + half];
#pragma unroll
                    for (int q = 0; q < 4; ++q) {
                        float v = fminf(fmaxf(a[q], -FP16MAX), FP16MAX);
                        a[q] = v;
                        ssp[mt][q >> 1] += v * v;
                    }
                }
#pragma unroll
        for (int mt = 0; mt < 2; ++mt)
#pragma unroll
            for (int hh = 0; hh < 2; ++hh) {
                float s0 = ssp[mt][hh];
                s0 += __shfl_xor_sync(0xffffffffu, s0, 1);
                s0 += __shfl_xor_sync(0xffffffffu, s0, 2);
                if ((lane & 3) == 0) {
                    const int row = wm * 32 + mt * 16 + (lane >> 2) + hh * 8;
                    ssm[wn * 128 + row] = s0;
                }
            }
        __syncthreads();
        const float post = (group == 0) ? ATTN_SCALE_L2E : 1.0f;
#pragma unroll
        for (int mt = 0; mt < 2; ++mt)
#pragma unroll
            for (int hh = 0; hh < 2; ++hh) {
                const int row = wm * 32 + mt * 16 + (lane >> 2) + hh * 8;
                const float tot = ssm[row] + ssm[128 + row];
                const float sc = rsqrtf(tot * (1.0f / 128.0f) + RMS_EPS) * post;
#pragma unroll
                for (int bt = 0; bt < 4; ++bt)
#pragma unroll
                    for (int half = 0; half < 2; ++half) {
                        acc[mt * 8 + bt * 2 + half][hh * 2 + 0] *= sc;
                        acc[mt * 8 + bt * 2 + half][hh * 2 + 1] *= sc;
                    }
            }
    }

    if (mode) {
        // q,k,v,gate all fp16. Layout [b][h][s][d].
        const int hh = (bn >> 7) & 15;
        __half* dsth = (group == 0) ? g_qh : (group == 1) ? g_kh
                     : (group == 2) ? g_vh : g_gate;
#pragma unroll
        for (int mt = 0; mt < 2; ++mt)
#pragma unroll
            for (int bt = 0; bt < 4; ++bt)
#pragma unroll
                for (int half = 0; half < 2; ++half) {
                    const int d = wn * 64 + bt * 16 + half * 8 + (lane & 3) * 2;
                    float* a = acc[mt * 8 + bt * 2 + half];
#pragma unroll
                    for (int rr = 0; rr < 2; ++rr) {
                        const int row = bm + wm * 32 + mt * 16 + (lane >> 2) + rr * 8;
                        const int bb = row >> 11, s = row & 2047;
                        const size_t idx = ((size_t)(bb * HEADS + hh) * SEQ + s) * HD + d;
                        *(uint32_t*)(dsth + idx) = roundh2(a[rr * 2 + 0], a[rr * 2 + 1]);
                    }
                }
    } else {
#pragma unroll
        for (int mt = 0; mt < 2; ++mt)
#pragma unroll
            for (int bt = 0; bt < 4; ++bt)
#pragma unroll
                for (int half = 0; half < 2; ++half) {
                    const int col = bn + wn * 64 + bt * 16 + half * 8 + (lane & 3) * 2;
                    const int r0 = bm + wm * 32 + mt * 16 + (lane >> 2);
                    float* a = acc[mt * 8 + bt * 2 + half];
                    *(float2*)(C + (size_t)r0 * N + col)       = make_float2(a[0], a[1]);
                    *(float2*)(C + (size_t)(r0 + 8) * N + col) = make_float2(a[2], a[3]);
                }
    }
}

// ---------------- HMMA fp16 1-term flash attention ----------------
// 512 threads = 16 warps, each warp 16 q rows -> 256 q rows per CTA.
// KV chunks of 64, double buffered. exp2 softmax. Software-pipelined ldsm.
#define AROWB 272                        // 128 fp16 = 256 B + 16 pad
#define QROWS 256
#define QT (QROWS * AROWB)               // 69632
#define KVR 64
#define KVB (KVR * AROWB)                // 17408
#define STG (2 * KVB)                    // k + v = 34816
#define ATTN_SMEM (QT + 2 * STG)         // 139264

__global__ __launch_bounds__(512, 1)
void attn_hmma()
{
    extern __shared__ char smraw[];
    const uint32_t sb = smem_u32(smraw);

    const int tid = threadIdx.x, w = tid >> 5, lane = tid & 31;
    const int qt = blockIdx.x, h = blockIdx.y, b = blockIdx.z;
    const size_t hb = ((size_t)b * HEADS + h) * SEQ;

    const __half* Qh_g = g_qh + (hb + qt * QROWS) * HD;
    const __half* Kh_g = g_kh + hb * HD;
    const __half* Vh_g = g_vh + hb * HD;

    auto loadKV = [&](int s, int kt) {
        const uint32_t base = sb + QT + s * STG;
        const size_t kv0 = (size_t)kt * KVR;
#pragma unroll
        for (int i = 0; i < 2; ++i) {
            const int v = tid + i * 512;
            const int row = v >> 4, c = v & 15;
            const uint32_t so = base + row * AROWB + c * 16;
            const size_t go = (kv0 + row) * HD + c * 8;
            cp16(so,       Kh_g + go);
            cp16(so + KVB, Vh_g + go);
        }
    };

#pragma unroll
    for (int i = 0; i < 8; ++i) {
        const int v = tid + i * 512;
        const int row = v >> 4, c = v & 15;
        cp16(sb + row * AROWB + c * 16, Qh_g + (size_t)row * HD + c * 8);
    }
    loadKV(0, 0); cp_commit();
    loadKV(1, 1); cp_commit();
    cp_wait<1>();
    __syncthreads();

    float oacc[16][4];
#pragma unroll
    for (int i = 0; i < 16; ++i)
#pragma unroll
        for (int j = 0; j < 4; ++j) oacc[i][j] = 0.f;
    float m0 = -INFINITY, m1 = -INFINITY, l0 = 0.f, l1 = 0.f;

    const uint32_t qro = (uint32_t)(w * 16 + (lane & 15)) * AROWB + (lane >> 4) * 16;
    const uint32_t kro = (uint32_t)(lane & 15) * AROWB + (lane >> 4) * 16;
    const uint32_t vro = (uint32_t)(lane & 15) * AROWB + (lane >> 4) * 16;

    const int nkt = SEQ / KVR;   // 32
    for (int c = 0; c < nkt; ++c) {
        const int s = c & 1;
        const uint32_t kbase = sb + QT + s * STG;

        // ---- S = q @ K^T (1-term, 16q x 64kv), pipelined ----
        float sacc[8][4];
#pragma unroll
        for (int i = 0; i < 8; ++i)
#pragma unroll
            for (int j = 0; j < 4; ++j) sacc[i][j] = 0.f;

        uint32_t ahb[2][4], bhb[2][4];
        ldsm4(ahb[0], sb + qro);
        ldsm4(bhb[0], kbase + kro);
#pragma unroll
        for (int kt = 0; kt < 8; ++kt) {
#pragma unroll
            for (int g = 0; g < 4; ++g) {
                const int cur = g & 1;
                if (g < 3) {
                    ldsm4(bhb[cur ^ 1], kbase + kro + (g + 1) * 16 * AROWB + kt * 32);
                } else if (kt < 7) {
                    ldsm4(ahb[(kt + 1) & 1], sb + qro + (kt + 1) * 32);
                    ldsm4(bhb[cur ^ 1], kbase + kro + (kt + 1) * 32);
                }
                uint32_t* bh = bhb[cur];
                const uint32_t b0[2] = { bh[0], bh[2] }, b1[2] = { bh[1], bh[3] };
                mma16816(sacc[2 * g + 0], ahb[kt & 1], b0);
                mma16816(sacc[2 * g + 1], ahb[kt & 1], b1);
            }
        }

        // ---- online softmax (exp2 domain) ----
        float mx0 = -INFINITY, mx1 = -INFINITY;
#pragma unroll
        for (int j = 0; j < 8; ++j) {
            mx0 = fmaxf(mx0, fmaxf(sacc[j][0], sacc[j][1]));
            mx1 = fmaxf(mx1, fmaxf(sacc[j][2], sacc[j][3]));
        }
        mx0 = fmaxf(mx0, __shfl_xor_sync(0xffffffffu, mx0, 1));
        mx0 = fmaxf(mx0, __shfl_xor_sync(0xffffffffu, mx0, 2));
        mx1 = fmaxf(mx1, __shfl_xor_sync(0xffffffffu, mx1, 1));
        mx1 = fmaxf(mx1, __shfl_xor_sync(0xffffffffu, mx1, 2));
        const float mn0 = fmaxf(m0, mx0), mn1 = fmaxf(m1, mx1);
        const float corr0 = exp2fa(m0 - mn0), corr1 = exp2fa(m1 - mn1);
        m0 = mn0; m1 = mn1;
        float rs0 = 0.f, rs1 = 0.f;
#pragma unroll
        for (int j = 0; j < 8; ++j) {
            sacc[j][0] = exp2fa(sacc[j][0] - mn0);
            sacc[j][1] = exp2fa(sacc[j][1] - mn0);
            sacc[j][2] = exp2fa(sacc[j][2] - mn1);
            sacc[j][3] = exp2fa(sacc[j][3] - mn1);
            rs0 += sacc[j][0] + sacc[j][1];
            rs1 += sacc[j][2] + sacc[j][3];
        }
        rs0 += __shfl_xor_sync(0xffffffffu, rs0, 1);
        rs0 += __shfl_xor_sync(0xffffffffu, rs0, 2);
        rs1 += __shfl_xor_sync(0xffffffffu, rs1, 1);
        rs1 += __shfl_xor_sync(0xffffffffu, rs1, 2);
        l0 = l0 * corr0 + rs0;
        l1 = l1 * corr1 + rs1;
        const bool need = (corr0 != 1.0f) || (corr1 != 1.0f);
        if (__any_sync(0xffffffffu, need)) {
#pragma unroll
            for (int n = 0; n < 16; ++n) {
                oacc[n][0] *= corr0; oacc[n][1] *= corr0;
                oacc[n][2] *= corr1; oacc[n][3] *= corr1;
            }
        }

        // ---- O += P @ V (P rounded per k16; V ldsm pipelined) ----
        uint32_t vhb[2][4];
        ldsm4t(vhb[0], kbase + KVB + vro);
#pragma unroll
        for (int kc = 0; kc < 4; ++kc) {
            uint32_t pa[4];
            pa[0] = roundh2(sacc[2 * kc][0],     sacc[2 * kc][1]);
            pa[1] = roundh2(sacc[2 * kc][2],     sacc[2 * kc][3]);
            pa[2] = roundh2(sacc[2 * kc + 1][0], sacc[2 * kc + 1][1]);
            pa[3] = roundh2(sacc[2 * kc + 1][2], sacc[2 * kc + 1][3]);
#pragma unroll
            for (int g2 = 0; g2 < 8; ++g2) {
                const int cur = g2 & 1;
                if (g2 < 7) {
                    ldsm4t(vhb[cur ^ 1], kbase + KVB + vro + kc * 16 * AROWB
                                       + (g2 + 1) * 32);
                } else if (kc < 3) {
                    ldsm4t(vhb[cur ^ 1], kbase + KVB + vro + (kc + 1) * 16 * AROWB);
                }
                uint32_t* vh = vhb[cur];
                const uint32_t b0[2] = { vh[0], vh[1] }, b1[2] = { vh[2], vh[3] };
                mma16816(oacc[2 * g2 + 0], pa, b0);
                mma16816(oacc[2 * g2 + 1], pa, b1);
            }
        }

        __syncthreads();
        if (c + 2 < nkt) {
            loadKV(s, c + 2);
            cp_commit();
            cp_wait<1>();
        } else {
            cp_wait<0>();
        }
        __syncthreads();
    }

    // ---- epilogue: O/l, sigmoid gate, rounded fp16 for GEMM2 ----
    const float inv0 = 1.0f / l0, inv1 = 1.0f / l1;
    const int r0 = w * 16 + (lane >> 2);
#pragma unroll
    for (int n = 0; n < 16; ++n) {
        const int d = n * 8 + (lane & 3) * 2;
#pragma unroll
        for (int rr = 0; rr < 2; ++rr) {
            const int qrow = qt * QROWS + r0 + rr * 8;
            const float inv = rr ? inv1 : inv0;
            const uint32_t gw = *(const uint32_t*)(g_gate + (hb + qrow) * HD + d);
            const float2 gv = __half22float2(*(const __half2*)&gw);
            const float sg0 = 1.0f / (1.0f + __expf(-gv.x));
            const float sg1 = 1.0f / (1.0f + __expf(-gv.y));
            const float x = sg0 * oacc[n][rr * 2 + 0] * inv;
            const float y = sg1 * oacc[n][rr * 2 + 1] * inv;
            const size_t o = (size_t)(b * SEQ + qrow) * DMODEL + h * HD + d;
            *(uint32_t*)(g_th + o) = roundh2(x, y);
        }
    }
}

// ---------------------------------------------------------------------------
extern "C" void kernel_launch(void* const* d_in, const int* in_sizes, int n_in,
                              void* d_out, int out_size)
{
    const float* hidden = (const float*)d_in[0];
    const float* W_in   = (const float*)d_in[1];
    const float* W_out  = (const float*)d_in[2];
    float* out = (float*)d_out;

    __half *ah, *win, *wo, *th;
    cudaGetSymbolAddress((void**)&ah,  g_ah);
    cudaGetSymbolAddress((void**)&win, g_win);
    cudaGetSymbolAddress((void**)&wo,  g_wo);
    cudaGetSymbolAddress((void**)&th,  g_th);

    cudaFuncSetAttribute(gemm_hmma,
                         cudaFuncAttributeMaxDynamicSharedMemorySize, GSMEM);
    cudaFuncSetAttribute(attn_hmma,
                         cudaFuncAttributeMaxDynamicSharedMemorySize, ATTN_SMEM);

    // 0) fused prep: hidden->fp16, W_in->fp16 T, W_out->fp16 T (one launch)
    prep_all<<<PREP_BLKS, 256>>>(hidden, W_in, W_out);

    // 1) proj GEMM (1-term fp16, pipelined ldsm) -> q/k/v/gate fp16
    gemm_hmma<<<dim3(NPROJ / BN, ROWS / BM), 256, GSMEM>>>(
        ah, win, nullptr, ROWS, NPROJ, DMODEL, 1);

    // 2) fp16 1-term flash attention (exp2 softmax, pipelined) -> g_th
    attn_hmma<<<dim3(SEQ / QROWS, HEADS, NB), 512, ATTN_SMEM>>>();

    // 3) out = att @ W_out (1-term fp16)
    gemm_hmma<<<dim3(DMODEL / BN, ROWS / BM), 256, GSMEM>>>(
        th, wo, out, ROWS, DMODEL, DMODEL, 0);
}

// round 16
// speedup vs baseline: 1.1329x; 1.1090x over previous
#include <cuda_runtime.h>
#include <cuda_fp16.h>
#include <math.h>
#include <stdint.h>

// Problem constants
#define ROWS   4096          // B*S
#define DMODEL 2048
#define NPROJ  8192          // 4*DMODEL
#define HEADS  16
#define HD     128
#define SEQ    2048
#define NB     2
#define FP16MAX 65504.0f
#define RMS_EPS 1e-5f
// 1/sqrt(128) * log2(e): q pre-scale so softmax can use exp2 directly
#define ATTN_SCALE_L2E (0.08838834764831845f * 1.4426950408889634f)

// ---------------- scratch (allocation-free) ----------------
#define HSD ((size_t)NB * HEADS * SEQ * HD)
__device__ __half g_qh[HSD];                 // q fp16 (rmsnorm*scale*log2e folded)
__device__ __half g_kh[HSD];                 // k fp16
__device__ __half g_vh[HSD];                 // v fp16
__device__ __half g_gate[HSD];               // gate fp16
__device__ __half g_ah  [(size_t)ROWS * DMODEL];   // hidden rounded fp16 [M,K]
__device__ __half g_win [(size_t)DMODEL * NPROJ];  // W_in rounded fp16 [K,N] (native)
__device__ __half g_wo  [(size_t)DMODEL * DMODEL]; // W_out rounded fp16 [K,N] (native)
__device__ __half g_th  [(size_t)ROWS * DMODEL];   // attn out rounded fp16

// ---------------- PTX helpers (sm_80-portable only) ----------------
__device__ __forceinline__ uint32_t smem_u32(const void* p) {
    uint32_t a;
    asm("{ .reg .u64 t; cvta.to.shared.u64 t, %1; cvt.u32.u64 %0, t; }" : "=r"(a) : "l"(p));
    return a;
}
__device__ __forceinline__ void cp16(uint32_t saddr, const void* g) {
    asm volatile("cp.async.cg.shared.global [%0], [%1], 16;" :: "r"(saddr), "l"(g));
}
__device__ __forceinline__ void cp_commit() {
    asm volatile("cp.async.commit_group;" ::: "memory");
}
template <int N>
__device__ __forceinline__ void cp_wait() {
    asm volatile("cp.async.wait_group %0;" :: "n"(N) : "memory");
}
__device__ __forceinline__ void ldsm4(uint32_t* r, uint32_t a) {
    asm volatile("ldmatrix.sync.aligned.m8n8.x4.shared.b16 {%0,%1,%2,%3}, [%4];"
                 : "=r"(r[0]), "=r"(r[1]), "=r"(r[2]), "=r"(r[3]) : "r"(a));
}
__device__ __forceinline__ void ldsm4t(uint32_t* r, uint32_t a) {
    asm volatile("ldmatrix.sync.aligned.m8n8.x4.trans.shared.b16 {%0,%1,%2,%3}, [%4];"
                 : "=r"(r[0]), "=r"(r[1]), "=r"(r[2]), "=r"(r[3]) : "r"(a));
}
__device__ __forceinline__ void mma16816(float* c, const uint32_t* a, const uint32_t* b) {
    asm volatile(
        "mma.sync.aligned.m16n8k16.row.col.f32.f16.f16.f32 "
        "{%0,%1,%2,%3}, {%4,%5,%6,%7}, {%8,%9}, {%0,%1,%2,%3};"
        : "+f"(c[0]), "+f"(c[1]), "+f"(c[2]), "+f"(c[3])
        : "r"(a[0]), "r"(a[1]), "r"(a[2]), "r"(a[3]), "r"(b[0]), "r"(b[1]));
}
__device__ __forceinline__ uint32_t roundh2(float x, float y) {
    __half2 h2 = __floats2half2_rn(x, y);
    return *(uint32_t*)&h2;
}
__device__ __forceinline__ float exp2fa(float x) {
    float r;
    asm("ex2.approx.f32 %0, %1;" : "=f"(r) : "f"(x));
    return r;
}

// ---------------- prep: three coalesced fp32->fp16 rounds, one launch ----------------
#define HID_BLKS 1024
#define WIN_BLKS 2048
#define WO_BLKS  512
#define PREP_BLKS (HID_BLKS + WIN_BLKS + WO_BLKS)

__device__ __forceinline__ void round_seg(const float* __restrict__ in,
                                          __half* __restrict__ outp,
                                          size_t n4, int blk0, int nblk,
                                          int bid, int tid)
{
    size_t i = (size_t)(bid - blk0) * 256 + tid;
    const size_t stride = (size_t)nblk * 256;
    for (; i < n4; i += stride) {
        float4 x = ((const float4*)in)[i];
        ((uint32_t*)outp)[i * 2 + 0] = roundh2(x.x, x.y);
        ((uint32_t*)outp)[i * 2 + 1] = roundh2(x.z, x.w);
    }
}

__global__ __launch_bounds__(256)
void prep_all(const float* __restrict__ hidden,
              const float* __restrict__ W_in,
              const float* __restrict__ W_out)
{
    const int bid = blockIdx.x, tid = threadIdx.x;
    if (bid < HID_BLKS) {
        round_seg(hidden, g_ah, (size_t)ROWS * DMODEL / 4, 0, HID_BLKS, bid, tid);
    } else if (bid < HID_BLKS + WIN_BLKS) {
        round_seg(W_in, g_win, (size_t)DMODEL * NPROJ / 4, HID_BLKS, WIN_BLKS, bid, tid);
    } else {
        round_seg(W_out, g_wo, (size_t)DMODEL * DMODEL / 4,
                  HID_BLKS + WIN_BLKS, WO_BLKS, bid, tid);
    }
}

// ---------------- HMMA fp16 1-term GEMM: C[M,N] = A[M,K] @ B[K,N] ----------------
// A [M,K] row-major (ldsm), B [K,N] row-major NATIVE (ldsm.trans, V-style).
// 128x128 block tile, BK=64, 8 warps (4m x 2n), 2-stage cp.async.
#define BM 128
#define BN 128
#define BK 64
#define AROWB_G 144                 // A row: 64 fp16 = 128 B + 16 pad
#define BROWB_G 272                 // B row: 128 fp16 = 256 B + 16 pad
#define A_TILEB (BM * AROWB_G)      // 18432
#define B_TILEB (BK * BROWB_G)      // 17408
#define STAGEB (A_TILEB + B_TILEB)  // 35840
#define GSMEM (2 * STAGEB)          // 71680

__global__ __launch_bounds__(256)
void gemm_hmma(const __half* __restrict__ A, const __half* __restrict__ B,
               float* __restrict__ C, int M, int N, int K, int mode)
{
    extern __shared__ char smraw[];
    const uint32_t sb = smem_u32(smraw);

    const int tid = threadIdx.x, wid = tid >> 5, lane = tid & 31;
    const int bm = blockIdx.y * BM, bn = blockIdx.x * BN;
    const int wm = wid >> 1, wn = wid & 1;

    const __half* A_p = A + (size_t)bm * K;
    const int nk = K / BK;

    auto stage_load = [&](int s, int kc) {
        const uint32_t base = sb + s * STAGEB;
        const size_t kofs = (size_t)kc * BK;
        // A: 128 rows x 8 chunks of 16B
#pragma unroll
        for (int i = 0; i < 4; ++i) {
            const int v = tid + i * 256;
            const int row = v >> 3, c = v & 7;
            cp16(base + row * AROWB_G + c * 16, A_p + (size_t)row * K + kofs + c * 8);
        }
        // B: 64 k-rows x 16 chunks of 16B (native [K,N])
#pragma unroll
        for (int i = 0; i < 4; ++i) {
            const int v = tid + i * 256;
            const int row = v >> 4, c = v & 15;
            cp16(base + A_TILEB + row * BROWB_G + c * 16,
                 B + (kofs + row) * (size_t)N + bn + c * 8);
        }
    };

    float acc[16][4];
#pragma unroll
    for (int i = 0; i < 16; ++i)
#pragma unroll
        for (int j = 0; j < 4; ++j) acc[i][j] = 0.f;

    stage_load(0, 0); cp_commit();
    stage_load(1, 1); cp_commit();
    cp_wait<1>();
    __syncthreads();

    for (int c = 0; c < nk; ++c) {
        const int s = c & 1;
        const uint32_t Ah = sb + s * STAGEB;
        const uint32_t Bh = Ah + A_TILEB;

#pragma unroll
        for (int ks = 0; ks < 4; ++ks) {
            uint32_t af[2][4];
#pragma unroll
            for (int mt = 0; mt < 2; ++mt) {
                const uint32_t ro = (uint32_t)(wm * 32 + mt * 16 + (lane & 15)) * AROWB_G
                                  + ks * 32 + (lane >> 4) * 16;
                ldsm4(af[mt], Ah + ro);
            }
#pragma unroll
            for (int bt = 0; bt < 4; ++bt) {
                // B fragment via ldsm.trans from [K,N] tile (V-style)
                const uint32_t ro = (uint32_t)(ks * 16 + (lane & 15)) * BROWB_G
                                  + (wn * 64 + bt * 16 + (lane >> 4) * 8) * 2;
                uint32_t bf[4];
                ldsm4t(bf, Bh + ro);
                const uint32_t b0[2] = { bf[0], bf[1] }, b1[2] = { bf[2], bf[3] };
#pragma unroll
                for (int mt = 0; mt < 2; ++mt) {
                    mma16816(acc[mt * 8 + bt * 2 + 0], af[mt], b0);
                    mma16816(acc[mt * 8 + bt * 2 + 1], af[mt], b1);
                }
            }
        }

        __syncthreads();
        if (c + 2 < nk) {
            stage_load(s, c + 2);
            cp_commit();
            cp_wait<1>();
        } else {
            cp_wait<0>();
        }
        __syncthreads();
    }

    const int group = bn >> 11;       // 0=q 1=k 2=v 3=g (mode 1 only)

    // ---- fused clamp+RMSNorm for q,k (mode 1) ----
    float* ssm = (float*)smraw;
    if (mode && group < 2) {
        float ssp[2][2] = { {0.f, 0.f}, {0.f, 0.f} };
#pragma unroll
        for (int mt = 0; mt < 2; ++mt)
#pragma unroll
            for (int bt = 0; bt < 4; ++bt)
#pragma unroll
                for (int half = 0; half < 2; ++half) {
                    float* a = acc[mt * 8 + bt * 2 + half];
#pragma unroll
                    for (int q = 0; q < 4; ++q) {
                        float v = fminf(fmaxf(a[q], -FP16MAX), FP16MAX);
                        a[q] = v;
                        ssp[mt][q >> 1] += v * v;
                    }
                }
#pragma unroll
        for (int mt = 0; mt < 2; ++mt)
#pragma unroll
            for (int hh = 0; hh < 2; ++hh) {
                float s0 = ssp[mt][hh];
                s0 += __shfl_xor_sync(0xffffffffu, s0, 1);
                s0 += __shfl_xor_sync(0xffffffffu, s0, 2);
                if ((lane & 3) == 0) {
                    const int row = wm * 32 + mt * 16 + (lane >> 2) + hh * 8;
                    ssm[wn * 128 + row] = s0;
                }
            }
        __syncthreads();
        const float post = (group == 0) ? ATTN_SCALE_L2E : 1.0f;
#pragma unroll
        for (int mt = 0; mt < 2; ++mt)
#pragma unroll
            for (int hh = 0; hh < 2; ++hh) {
                const int row = wm * 32 + mt * 16 + (lane >> 2) + hh * 8;
                const float tot = ssm[row] + ssm[128 + row];
                const float sc = rsqrtf(tot * (1.0f / 128.0f) + RMS_EPS) * post;
#pragma unroll
                for (int bt = 0; bt < 4; ++bt)
#pragma unroll
                    for (int half = 0; half < 2; ++half) {
                        acc[mt * 8 + bt * 2 + half][hh * 2 + 0] *= sc;
                        acc[mt * 8 + bt * 2 + half][hh * 2 + 1] *= sc;
                    }
            }
    }

    if (mode) {
        // q,k,v,gate all fp16. Layout [b][h][s][d].
        const int hh = (bn >> 7) & 15;
        __half* dsth = (group == 0) ? g_qh : (group == 1) ? g_kh
                     : (group == 2) ? g_vh : g_gate;
#pragma unroll
        for (int mt = 0; mt < 2; ++mt)
#pragma unroll
            for (int bt = 0; bt < 4; ++bt)
#pragma unroll
                for (int half = 0; half < 2; ++half) {
                    const int d = wn * 64 + bt * 16 + half * 8 + (lane & 3) * 2;
                    float* a = acc[mt * 8 + bt * 2 + half];
#pragma unroll
                    for (int rr = 0; rr < 2; ++rr) {
                        const int row = bm + wm * 32 + mt * 16 + (lane >> 2) + rr * 8;
                        const int bb = row >> 11, s = row & 2047;
                        const size_t idx = ((size_t)(bb * HEADS + hh) * SEQ + s) * HD + d;
                        *(uint32_t*)(dsth + idx) = roundh2(a[rr * 2 + 0], a[rr * 2 + 1]);
                    }
                }
    } else {
#pragma unroll
        for (int mt = 0; mt < 2; ++mt)
#pragma unroll
            for (int bt = 0; bt < 4; ++bt)
#pragma unroll
                for (int half = 0; half < 2; ++half) {
                    const int col = bn + wn * 64 + bt * 16 + half * 8 + (lane & 3) * 2;
                    const int r0 = bm + wm * 32 + mt * 16 + (lane >> 2);
                    float* a = acc[mt * 8 + bt * 2 + half];
                    *(float2*)(C + (size_t)r0 * N + col)       = make_float2(a[0], a[1]);
                    *(float2*)(C + (size_t)(r0 + 8) * N + col) = make_float2(a[2], a[3]);
                }
    }
}

// ---------------- HMMA fp16 1-term flash attention (R13 config) ----------------
#define AROWB 272                        // 128 fp16 = 256 B + 16 pad
#define QROWS 256
#define QT (QROWS * AROWB)               // 69632
#define KVR 64
#define KVB (KVR * AROWB)                // 17408
#define STG (2 * KVB)                    // k + v = 34816
#define ATTN_SMEM (QT + 2 * STG)         // 139264

__global__ __launch_bounds__(512, 1)
void attn_hmma()
{
    extern __shared__ char smraw[];
    const uint32_t sb = smem_u32(smraw);

    const int tid = threadIdx.x, w = tid >> 5, lane = tid & 31;
    const int qt = blockIdx.x, h = blockIdx.y, b = blockIdx.z;
    const size_t hb = ((size_t)b * HEADS + h) * SEQ;

    const __half* Qh_g = g_qh + (hb + qt * QROWS) * HD;
    const __half* Kh_g = g_kh + hb * HD;
    const __half* Vh_g = g_vh + hb * HD;

    auto loadKV = [&](int s, int kt) {
        const uint32_t base = sb + QT + s * STG;
        const size_t kv0 = (size_t)kt * KVR;
#pragma unroll
        for (int i = 0; i < 2; ++i) {
            const int v = tid + i * 512;
            const int row = v >> 4, c = v & 15;
            const uint32_t so = base + row * AROWB + c * 16;
            const size_t go = (kv0 + row) * HD + c * 8;
            cp16(so,       Kh_g + go);
            cp16(so + KVB, Vh_g + go);
        }
    };

#pragma unroll
    for (int i = 0; i < 8; ++i) {
        const int v = tid + i * 512;
        const int row = v >> 4, c = v & 15;
        cp16(sb + row * AROWB + c * 16, Qh_g + (size_t)row * HD + c * 8);
    }
    loadKV(0, 0); cp_commit();
    loadKV(1, 1); cp_commit();
    cp_wait<1>();
    __syncthreads();

    float oacc[16][4];
#pragma unroll
    for (int i = 0; i < 16; ++i)
#pragma unroll
        for (int j = 0; j < 4; ++j) oacc[i][j] = 0.f;
    float m0 = -INFINITY, m1 = -INFINITY, l0 = 0.f, l1 = 0.f;

    const int nkt = SEQ / KVR;   // 32
    for (int c = 0; c < nkt; ++c) {
        const int s = c & 1;
        const uint32_t kbase = sb + QT + s * STG;

        // ---- S = q @ K^T (1-term, 16q x 64kv) ----
        float sacc[8][4];
#pragma unroll
        for (int i = 0; i < 8; ++i)
#pragma unroll
            for (int j = 0; j < 4; ++j) sacc[i][j] = 0.f;

#pragma unroll
        for (int kt = 0; kt < 8; ++kt) {
            uint32_t ah[4];
            const uint32_t qo = (uint32_t)(w * 16 + (lane & 15)) * AROWB
                              + kt * 32 + (lane >> 4) * 16;
            ldsm4(ah, sb + qo);
#pragma unroll
            for (int g = 0; g < 4; ++g) {
                const uint32_t ko = kbase + (uint32_t)(g * 16 + (lane & 15)) * AROWB
                                  + kt * 32 + (lane >> 4) * 16;
                uint32_t bh[4];
                ldsm4(bh, ko);
                const uint32_t b0[2] = { bh[0], bh[2] }, b1[2] = { bh[1], bh[3] };
                mma16816(sacc[2 * g + 0], ah, b0);
                mma16816(sacc[2 * g + 1], ah, b1);
            }
        }

        // ---- online softmax (exp2 domain) ----
        float mx0 = -INFINITY, mx1 = -INFINITY;
#pragma unroll
        for (int j = 0; j < 8; ++j) {
            mx0 = fmaxf(mx0, fmaxf(sacc[j][0], sacc[j][1]));
            mx1 = fmaxf(mx1, fmaxf(sacc[j][2], sacc[j][3]));
        }
        mx0 = fmaxf(mx0, __shfl_xor_sync(0xffffffffu, mx0, 1));
        mx0 = fmaxf(mx0, __shfl_xor_sync(0xffffffffu, mx0, 2));
        mx1 = fmaxf(mx1, __shfl_xor_sync(0xffffffffu, mx1, 1));
        mx1 = fmaxf(mx1, __shfl_xor_sync(0xffffffffu, mx1, 2));
        const float mn0 = fmaxf(m0, mx0), mn1 = fmaxf(m1, mx1);
        const float corr0 = exp2fa(m0 - mn0), corr1 = exp2fa(m1 - mn1);
        m0 = mn0; m1 = mn1;
        float rs0 = 0.f, rs1 = 0.f;
#pragma unroll
        for (int j = 0; j < 8; ++j) {
            sacc[j][0] = exp2fa(sacc[j][0] - mn0);
            sacc[j][1] = exp2fa(sacc[j][1] - mn0);
            sacc[j][2] = exp2fa(sacc[j][2] - mn1);
            sacc[j][3] = exp2fa(sacc[j][3] - mn1);
            rs0 += sacc[j][0] + sacc[j][1];
            rs1 += sacc[j][2] + sacc[j][3];
        }
        rs0 += __shfl_xor_sync(0xffffffffu, rs0, 1);
        rs0 += __shfl_xor_sync(0xffffffffu, rs0, 2);
        rs1 += __shfl_xor_sync(0xffffffffu, rs1, 1);
        rs1 += __shfl_xor_sync(0xffffffffu, rs1, 2);
        l0 = l0 * corr0 + rs0;
        l1 = l1 * corr1 + rs1;
        const bool need = (corr0 != 1.0f) || (corr1 != 1.0f);
        if (__any_sync(0xffffffffu, need)) {
#pragma unroll
            for (int n = 0; n < 16; ++n) {
                oacc[n][0] *= corr0; oacc[n][1] *= corr0;
                oacc[n][2] *= corr1; oacc[n][3] *= corr1;
            }
        }

        // ---- O += P @ V (P rounded to fp16 per k16 group) ----
#pragma unroll
        for (int kc = 0; kc < 4; ++kc) {
            uint32_t pa[4];
            pa[0] = roundh2(sacc[2 * kc][0],     sacc[2 * kc][1]);
            pa[1] = roundh2(sacc[2 * kc][2],     sacc[2 * kc][3]);
            pa[2] = roundh2(sacc[2 * kc + 1][0], sacc[2 * kc + 1][1]);
            pa[3] = roundh2(sacc[2 * kc + 1][2], sacc[2 * kc + 1][3]);
#pragma unroll
            for (int g2 = 0; g2 < 8; ++g2) {
                const uint32_t vo = kbase + KVB
                                  + (uint32_t)(kc * 16 + (lane & 15)) * AROWB
                                  + (g2 * 16 + (lane >> 4) * 8) * 2;
                uint32_t vh[4];
                ldsm4t(vh, vo);
                const uint32_t b0[2] = { vh[0], vh[1] }, b1[2] = { vh[2], vh[3] };
                mma16816(oacc[2 * g2 + 0], pa, b0);
                mma16816(oacc[2 * g2 + 1], pa, b1);
            }
        }

        __syncthreads();
        if (c + 2 < nkt) {
            loadKV(s, c + 2);
            cp_commit();
            cp_wait<1>();
        } else {
            cp_wait<0>();
        }
        __syncthreads();
    }

    // ---- epilogue: O/l, sigmoid gate, rounded fp16 for GEMM2 ----
    const float inv0 = 1.0f / l0, inv1 = 1.0f / l1;
    const int r0 = w * 16 + (lane >> 2);
#pragma unroll
    for (int n = 0; n < 16; ++n) {
        const int d = n * 8 + (lane & 3) * 2;
#pragma unroll
        for (int rr = 0; rr < 2; ++rr) {
            const int qrow = qt * QROWS + r0 + rr * 8;
            const float inv = rr ? inv1 : inv0;
            const uint32_t gw = *(const uint32_t*)(g_gate + (hb + qrow) * HD + d);
            const float2 gv = __half22float2(*(const __half2*)&gw);
            const float sg0 = 1.0f / (1.0f + __expf(-gv.x));
            const float sg1 = 1.0f / (1.0f + __expf(-gv.y));
            const float x = sg0 * oacc[n][rr * 2 + 0] * inv;
            const float y = sg1 * oacc[n][rr * 2 + 1] * inv;
            const size_t o = (size_t)(b * SEQ + qrow) * DMODEL + h * HD + d;
            *(uint32_t*)(g_th + o) = roundh2(x, y);
        }
    }
}

// ---------------------------------------------------------------------------
extern "C" void kernel_launch(void* const* d_in, const int* in_sizes, int n_in,
                              void* d_out, int out_size)
{
    const float* hidden = (const float*)d_in[0];
    const float* W_in   = (const float*)d_in[1];
    const float* W_out  = (const float*)d_in[2];
    float* out = (float*)d_out;

    __half *ah, *win, *wo, *th;
    cudaGetSymbolAddress((void**)&ah,  g_ah);
    cudaGetSymbolAddress((void**)&win, g_win);
    cudaGetSymbolAddress((void**)&wo,  g_wo);
    cudaGetSymbolAddress((void**)&th,  g_th);

    cudaFuncSetAttribute(gemm_hmma,
                         cudaFuncAttributeMaxDynamicSharedMemorySize, GSMEM);
    cudaFuncSetAttribute(attn_hmma,
                         cudaFuncAttributeMaxDynamicSharedMemorySize, ATTN_SMEM);

    // 0) prep: three coalesced fp32->fp16 rounds (no transposes), one launch
    prep_all<<<PREP_BLKS, 256>>>(hidden, W_in, W_out);

    // 1) proj GEMM (1-term fp16, B native [K,N] via ldsm.trans) -> q/k/v/gate
    gemm_hmma<<<dim3(NPROJ / BN, ROWS / BM), 256, GSMEM>>>(
        ah, win, nullptr, ROWS, NPROJ, DMODEL, 1);

    // 2) fp16 1-term flash attention (exp2 softmax) + sigmoid gate -> g_th
    attn_hmma<<<dim3(SEQ / QROWS, HEADS, NB), 512, ATTN_SMEM>>>();

    // 3) out = att @ W_out (1-term fp16, B native [K,N])
    gemm_hmma<<<dim3(DMODEL / BN, ROWS / BM), 256, GSMEM>>>(
        th, wo, out, ROWS, DMODEL, DMODEL, 0);
}